// round 9
// baseline (speedup 1.0000x reference)
#include <cuda_runtime.h>
#include <cuda_bf16.h>

#define N_NODES  100000
#define N_EDGES  3200000
#define N_GRAPHS 512
#define HID      16
#define LABELS   10
#define VOCAB    128

#define SCAN_BLK 1024
#define SCAN_NB  ((N_NODES + SCAN_BLK - 1) / SCAN_BLK)   // 98

// ---------------- scratch (device globals; no allocation allowed) ----------
__device__ int    g_deg   [N_NODES];
__device__ int    g_off   [N_NODES];
__device__ int    g_cursor[N_NODES];
__device__ int    g_bsum  [SCAN_NB];
__device__ int    g_bbase [SCAN_NB];
__device__ int    g_csr   [N_EDGES];
__device__ float  g_dinv  [N_NODES];
__device__ float4 g_a1    [N_NODES * 4];    // EW[x[i]] * dinv[i]
__device__ float4 g_a2    [N_NODES * 4];    // (h1 @ W2) * dinv[i]
__device__ float4 g_EW    [VOCAB * 4];      // emb @ W1
__device__ float  g_sums  [N_GRAPHS * HID];
__device__ float  g_cnt   [N_GRAPHS];

__device__ __forceinline__ void redf(float* p, float v) {
    asm volatile("red.global.add.f32 [%0], %1;" :: "l"(p), "f"(v) : "memory");
}
__device__ __forceinline__ void redu(int* p) {
    asm volatile("red.global.add.u32 [%0], %1;" :: "l"(p), "r"(1u) : "memory");
}

// ---------------- build ------------------------------------------------------

__global__ __launch_bounds__(256) void k_init() {
    int i = blockIdx.x * blockDim.x + threadIdx.x;
    if (i < N_NODES) g_deg[i] = 0;
    if (i < N_GRAPHS * HID) g_sums[i] = 0.0f;
    if (i < N_GRAPHS) g_cnt[i] = 0.0f;
}

__global__ __launch_bounds__(256) void k_deg(const int* __restrict__ dst, int E) {
    int e = blockIdx.x * blockDim.x + threadIdx.x;
    if (e < E) redu(&g_deg[dst[e]]);
}

// shfl-based block scan (1024/block), 2 barriers
__global__ __launch_bounds__(SCAN_BLK) void k_scan1() {
    __shared__ int wtot[32];
    int gid = blockIdx.x * SCAN_BLK + threadIdx.x;
    int lane = threadIdx.x & 31, wid = threadIdx.x >> 5;
    int v = (gid < N_NODES) ? g_deg[gid] : 0;
    int x = v;
#pragma unroll
    for (int o = 1; o < 32; o <<= 1) {
        int t = __shfl_up_sync(0xffffffffu, x, o);
        if (lane >= o) x += t;
    }
    if (lane == 31) wtot[wid] = x;
    __syncthreads();
    if (threadIdx.x < 32) {
        int w = wtot[threadIdx.x];
        int y = w;
#pragma unroll
        for (int o = 1; o < 32; o <<= 1) {
            int t = __shfl_up_sync(0xffffffffu, y, o);
            if (threadIdx.x >= o) y += t;
        }
        wtot[threadIdx.x] = y - w;           // exclusive warp base
        if (threadIdx.x == 31) g_bsum[blockIdx.x] = y;
    }
    __syncthreads();
    if (gid < N_NODES) g_off[gid] = x - v + wtot[wid];
}

// block 0: scan block totals; block 1: EW = emb @ W1
__global__ __launch_bounds__(128) void k_scan2_ew(const float* __restrict__ emb,
                                                  const float* __restrict__ W1) {
    int t = threadIdx.x;
    if (blockIdx.x == 0) {
        __shared__ int s[128];
        int v = (t < SCAN_NB) ? g_bsum[t] : 0;
        s[t] = v;
        __syncthreads();
#pragma unroll
        for (int off = 1; off < 128; off <<= 1) {
            int u = (t >= off) ? s[t - off] : 0;
            __syncthreads();
            s[t] += u;
            __syncthreads();
        }
        if (t < SCAN_NB) g_bbase[t] = s[t] - v;
    } else {
        __shared__ float sW[HID * HID];
        sW[t] = W1[t];
        sW[t + 128] = W1[t + 128];
        __syncthreads();
        float h[HID];
#pragma unroll
        for (int k = 0; k < HID; k++) h[k] = emb[t * HID + k];
#pragma unroll
        for (int q = 0; q < 4; q++) {
            float o[4];
#pragma unroll
            for (int jj = 0; jj < 4; jj++) {
                float s = 0.0f;
#pragma unroll
                for (int k = 0; k < HID; k++) s = fmaf(h[k], sW[k * HID + 4 * q + jj], s);
                o[jj] = s;
            }
            g_EW[t * 4 + q] = make_float4(o[0], o[1], o[2], o[3]);
        }
    }
}

// finalize offsets/cursors/dinv AND emit a1 = EW[x]*dinv
__global__ __launch_bounds__(256) void k_scan3_a1(const int* __restrict__ x) {
    int i = blockIdx.x * blockDim.x + threadIdx.x;
    if (i >= N_NODES) return;
    int o = g_off[i] + g_bbase[i >> 10];
    g_off[i] = o;
    g_cursor[i] = o;
    float di = rsqrtf((float)g_deg[i] + 1.0f);
    g_dinv[i] = di;
    const float4* r = &g_EW[x[i] * 4];
#pragma unroll
    for (int q = 0; q < 4; q++) {
        float4 v = r[q];
        g_a1[i * 4 + q] = make_float4(v.x * di, v.y * di, v.z * di, v.w * di);
    }
}

__global__ __launch_bounds__(256) void k_scatter(const int* __restrict__ src,
                                                 const int* __restrict__ dst, int E) {
    int e = blockIdx.x * blockDim.x + threadIdx.x;
    if (e >= E) return;
    int pos = atomicAdd(&g_cursor[dst[e]], 1);
    g_csr[pos] = src[e];
}

// ---------------- gather core (warp/node, 4 lanes per edge) ------------------
// leaves lanes 0-3 holding the float4 chunks of  sum_{s->n} val[s]
__device__ __forceinline__ float4 gather_acc(const float4* __restrict__ val,
                                             int node, int lane) {
    int eq = lane >> 2, fj = lane & 3;
    int off = __ldg(&g_off[node]);
    int deg = __ldg(&g_deg[node]);
    float4 acc = make_float4(0.f, 0.f, 0.f, 0.f);
    for (int base = 0; base < deg; base += 8) {
        int e = base + eq;
        if (e < deg) {
            int s = __ldg(&g_csr[off + e]);
            float4 v = __ldg(&val[s * 4 + fj]);
            acc.x += v.x; acc.y += v.y; acc.z += v.z; acc.w += v.w;
        }
    }
#pragma unroll
    for (int o = 16; o >= 4; o >>= 1) {
        acc.x += __shfl_down_sync(0xffffffffu, acc.x, o);
        acc.y += __shfl_down_sync(0xffffffffu, acc.y, o);
        acc.z += __shfl_down_sync(0xffffffffu, acc.z, o);
        acc.w += __shfl_down_sync(0xffffffffu, acc.w, o);
    }
    return acc;
}

// layer1 gather + relu + (h1@W2)*dinv  -> g_a2   (h1 never materialized)
__global__ __launch_bounds__(256) void k_gather1_l2(const float* __restrict__ b1,
                                                    const float* __restrict__ W2) {
    __shared__ float sW[HID * HID];
    if (threadIdx.x < HID * HID) sW[threadIdx.x] = W2[threadIdx.x];
    __syncthreads();
    int n = (blockIdx.x * blockDim.x + threadIdx.x) >> 5;
    if (n >= N_NODES) return;
    int lane = threadIdx.x & 31;
    float4 acc = gather_acc(g_a1, n, lane);
    if (lane < 4) {
        float di = __ldg(&g_dinv[n]);
        float4 self = __ldg(&g_a1[n * 4 + lane]);
        float4 b = __ldg((const float4*)b1 + lane);
        float4 h;
        h.x = fmaxf((acc.x + self.x) * di + b.x, 0.0f);
        h.y = fmaxf((acc.y + self.y) * di + b.y, 0.0f);
        h.z = fmaxf((acc.z + self.z) * di + b.z, 0.0f);
        h.w = fmaxf((acc.w + self.w) * di + b.w, 0.0f);
        // o[jb..jb+3] = sum_k h[k] * W2[k][jb..jb+3], h spread over lanes 0-3
        int jb = lane * 4;
        float ox = 0.f, oy = 0.f, oz = 0.f, ow = 0.f;
#pragma unroll
        for (int m = 0; m < 4; m++) {
            float4 hm;
            hm.x = __shfl_sync(0x0000000fu, h.x, m);
            hm.y = __shfl_sync(0x0000000fu, h.y, m);
            hm.z = __shfl_sync(0x0000000fu, h.z, m);
            hm.w = __shfl_sync(0x0000000fu, h.w, m);
            const float* w0 = &sW[(4 * m + 0) * HID + jb];
            const float* w1 = &sW[(4 * m + 1) * HID + jb];
            const float* w2 = &sW[(4 * m + 2) * HID + jb];
            const float* w3 = &sW[(4 * m + 3) * HID + jb];
            ox = fmaf(hm.x, w0[0], ox); oy = fmaf(hm.x, w0[1], oy);
            oz = fmaf(hm.x, w0[2], oz); ow = fmaf(hm.x, w0[3], ow);
            ox = fmaf(hm.y, w1[0], ox); oy = fmaf(hm.y, w1[1], oy);
            oz = fmaf(hm.y, w1[2], oz); ow = fmaf(hm.y, w1[3], ow);
            ox = fmaf(hm.z, w2[0], ox); oy = fmaf(hm.z, w2[1], oy);
            oz = fmaf(hm.z, w2[2], oz); ow = fmaf(hm.z, w2[3], ow);
            ox = fmaf(hm.w, w3[0], ox); oy = fmaf(hm.w, w3[1], oy);
            oz = fmaf(hm.w, w3[2], oz); ow = fmaf(hm.w, w3[3], ow);
        }
        g_a2[n * 4 + lane] = make_float4(ox * di, oy * di, oz * di, ow * di);
    }
}

// layer2 gather + relu + mean-pool reduction (h2 never materialized)
__global__ __launch_bounds__(256) void k_gather2_pool(const float* __restrict__ b2,
                                                      const int* __restrict__ batch) {
    __shared__ float sh[8][HID];
    __shared__ int   sb[8];
    int tid = threadIdx.x;
    int wib = tid >> 5, lane = tid & 31;
    int n = (blockIdx.x * blockDim.x + tid) >> 5;
    bool valid = (n < N_NODES);
    if (valid) {
        float4 acc = gather_acc(g_a2, n, lane);
        if (lane < 4) {
            float di = __ldg(&g_dinv[n]);
            float4 self = __ldg(&g_a2[n * 4 + lane]);
            float4 b = __ldg((const float4*)b2 + lane);
            sh[wib][4 * lane + 0] = fmaxf((acc.x + self.x) * di + b.x, 0.0f);
            sh[wib][4 * lane + 1] = fmaxf((acc.y + self.y) * di + b.y, 0.0f);
            sh[wib][4 * lane + 2] = fmaxf((acc.z + self.z) * di + b.z, 0.0f);
            sh[wib][4 * lane + 3] = fmaxf((acc.w + self.w) * di + b.w, 0.0f);
        }
    }
    if (lane == 0) sb[wib] = valid ? __ldg(&batch[n]) : -1;
    __syncthreads();
    if (tid < 32) {
        int b0 = sb[0], b7 = sb[7];
        if (b0 == b7 && b0 >= 0) {           // whole block one graph (common: batch sorted)
            if (lane < HID) {
                float s = 0.f;
#pragma unroll
                for (int r = 0; r < 8; r++) s += sh[r][lane];
                redf(&g_sums[b0 * HID + lane], s);
            }
            if (lane == 0) redf(&g_cnt[b0], 8.0f);
        } else {
            for (int r = 0; r < 8; r++) {
                int b = sb[r];
                if (b < 0) continue;
                if (lane < HID) redf(&g_sums[b * HID + lane], sh[r][lane]);
                if (lane == 0) redf(&g_cnt[b], 1.0f);
            }
        }
    }
}

__global__ __launch_bounds__(256) void k_final(const float* __restrict__ Wc,
                                               const float* __restrict__ bc,
                                               float* __restrict__ out) {
    int g = blockIdx.x * blockDim.x + threadIdx.x;
    if (g >= N_GRAPHS) return;
    float inv = 1.0f / fmaxf(g_cnt[g], 1.0f);
    float p[HID];
#pragma unroll
    for (int k = 0; k < HID; k++) p[k] = g_sums[g * HID + k] * inv;
#pragma unroll
    for (int j = 0; j < LABELS; j++) {
        float s = __ldg(&bc[j]);
#pragma unroll
        for (int k = 0; k < HID; k++) s = fmaf(p[k], __ldg(&Wc[k * LABELS + j]), s);
        out[g * LABELS + j] = s;
    }
}

// ---------------- launch -----------------------------------------------------
extern "C" void kernel_launch(void* const* d_in, const int* in_sizes, int n_in,
                              void* d_out, int out_size) {
    const int*   x    = (const int*)  d_in[0];
    const int*   ei   = (const int*)  d_in[1];
    const int*   batch= (const int*)  d_in[2];
    const float* emb  = (const float*)d_in[3];
    const float* W1   = (const float*)d_in[4];
    const float* b1   = (const float*)d_in[5];
    const float* W2   = (const float*)d_in[6];
    const float* b2   = (const float*)d_in[7];
    const float* Wc   = (const float*)d_in[8];
    const float* bc   = (const float*)d_in[9];
    float* out = (float*)d_out;

    int E = in_sizes[1] / 2;
    const int* src = ei;
    const int* dst = ei + E;

    int gn = (N_NODES + 255) / 256;
    int ge = (E + 255) / 256;
    int gw = (N_NODES * 32 + 255) / 256;     // warp per node

    k_init         <<<gn, 256>>>();
    k_deg          <<<ge, 256>>>(dst, E);
    k_scan1        <<<SCAN_NB, SCAN_BLK>>>();
    k_scan2_ew     <<<2, 128>>>(emb, W1);
    k_scan3_a1     <<<gn, 256>>>(x);
    k_scatter      <<<ge, 256>>>(src, dst, E);
    k_gather1_l2   <<<gw, 256>>>(b1, W2);
    k_gather2_pool <<<gw, 256>>>(b2, batch);
    k_final        <<<(N_GRAPHS + 255) / 256, 256>>>(Wc, bc, out);
}

// round 10
// speedup vs baseline: 1.0584x; 1.0584x over previous
#include <cuda_runtime.h>
#include <cuda_bf16.h>

#define N_NODES  100000
#define N_EDGES  3200000
#define N_GRAPHS 512
#define HID      16
#define LABELS   10
#define VOCAB    128

#define SCAN_BLK 1024
#define SCAN_NB  ((N_NODES + SCAN_BLK - 1) / SCAN_BLK)   // 98

// ---------------- scratch (device globals; no allocation allowed) ----------
__device__ int      g_deg   [N_NODES];
__device__ int      g_off   [N_NODES];
__device__ int      g_cursor[N_NODES];
__device__ int      g_bsum  [SCAN_NB];
__device__ int      g_bbase [SCAN_NB];
__device__ int2     g_csr2  [N_EDGES];      // {src, packed(dinv[src],x[src])} by dst
__device__ unsigned g_v     [N_NODES];      // packed: dinv (17-bit mant) | x (7 bits)
__device__ float    g_dinv  [N_NODES];
__device__ float4   g_h1    [N_NODES * 4];  // relu(layer1)
__device__ float4   g_a2    [N_NODES * 4];  // (h1 @ W2) * dinv[i]
__device__ float4   g_h2    [N_NODES * 4];  // relu(layer2)
__device__ float4   g_EW    [VOCAB * 4];    // emb @ W1   (128 x 16 = 8KB)
__device__ float    g_sums  [N_GRAPHS * HID];
__device__ float    g_cnt   [N_GRAPHS];

__device__ __forceinline__ void red4(float4* p, float a, float b, float c, float d) {
    asm volatile("red.global.add.v4.f32 [%0], {%1,%2,%3,%4};"
                 :: "l"(p), "f"(a), "f"(b), "f"(c), "f"(d) : "memory");
}
__device__ __forceinline__ void redu(int* p) {
    asm volatile("red.global.add.u32 [%0], %1;" :: "l"(p), "r"(1u) : "memory");
}

// ---------------- build ------------------------------------------------------

__global__ __launch_bounds__(256) void k_init() {
    int i = blockIdx.x * blockDim.x + threadIdx.x;
    if (i < N_NODES) g_deg[i] = 0;
    if (i < N_GRAPHS * HID) g_sums[i] = 0.0f;
    if (i < N_GRAPHS) g_cnt[i] = 0.0f;
}

__global__ __launch_bounds__(256) void k_deg(const int* __restrict__ dst, int E) {
    int e = blockIdx.x * blockDim.x + threadIdx.x;
    if (e < E) redu(&g_deg[dst[e]]);
}

// shfl-based block scan (1024/block)
__global__ __launch_bounds__(SCAN_BLK) void k_scan1() {
    __shared__ int wtot[32];
    int gid = blockIdx.x * SCAN_BLK + threadIdx.x;
    int lane = threadIdx.x & 31, wid = threadIdx.x >> 5;
    int v = (gid < N_NODES) ? g_deg[gid] : 0;
    int x = v;
#pragma unroll
    for (int o = 1; o < 32; o <<= 1) {
        int t = __shfl_up_sync(0xffffffffu, x, o);
        if (lane >= o) x += t;
    }
    if (lane == 31) wtot[wid] = x;
    __syncthreads();
    if (threadIdx.x < 32) {
        int w = wtot[threadIdx.x];
        int y = w;
#pragma unroll
        for (int o = 1; o < 32; o <<= 1) {
            int t = __shfl_up_sync(0xffffffffu, y, o);
            if (threadIdx.x >= o) y += t;
        }
        wtot[threadIdx.x] = y - w;
        if (threadIdx.x == 31) g_bsum[blockIdx.x] = y;
    }
    __syncthreads();
    if (gid < N_NODES) g_off[gid] = x - v + wtot[wid];
}

// block 0: scan block totals; block 1: EW = emb @ W1
__global__ __launch_bounds__(128) void k_scan2_ew(const float* __restrict__ emb,
                                                  const float* __restrict__ W1) {
    int t = threadIdx.x;
    if (blockIdx.x == 0) {
        __shared__ int s[128];
        int v = (t < SCAN_NB) ? g_bsum[t] : 0;
        s[t] = v;
        __syncthreads();
#pragma unroll
        for (int off = 1; off < 128; off <<= 1) {
            int u = (t >= off) ? s[t - off] : 0;
            __syncthreads();
            s[t] += u;
            __syncthreads();
        }
        if (t < SCAN_NB) g_bbase[t] = s[t] - v;
    } else {
        __shared__ float sW[HID * HID];
        sW[t] = W1[t];
        sW[t + 128] = W1[t + 128];
        __syncthreads();
        float h[HID];
#pragma unroll
        for (int k = 0; k < HID; k++) h[k] = emb[t * HID + k];
#pragma unroll
        for (int q = 0; q < 4; q++) {
            float o[4];
#pragma unroll
            for (int jj = 0; jj < 4; jj++) {
                float s = 0.0f;
#pragma unroll
                for (int k = 0; k < HID; k++) s = fmaf(h[k], sW[k * HID + 4 * q + jj], s);
                o[jj] = s;
            }
            g_EW[t * 4 + q] = make_float4(o[0], o[1], o[2], o[3]);
        }
    }
}

// finalize offsets/cursors/dinv AND pack v = (dinv rounded to 17-bit mant) | x
__global__ __launch_bounds__(256) void k_scan3_v(const int* __restrict__ x) {
    int i = blockIdx.x * blockDim.x + threadIdx.x;
    if (i >= N_NODES) return;
    int o = g_off[i] + g_bbase[i >> 10];
    g_off[i] = o;
    g_cursor[i] = o;
    float di = rsqrtf((float)g_deg[i] + 1.0f);
    g_dinv[i] = di;
    unsigned b = (__float_as_uint(di) + 0x40u) & ~0x7Fu;   // round-to-nearest at bit 7
    g_v[i] = b | (unsigned)x[i];
}

__global__ __launch_bounds__(256) void k_scatter(const int* __restrict__ src,
                                                 const int* __restrict__ dst, int E) {
    int e = blockIdx.x * blockDim.x + threadIdx.x;
    if (e >= E) return;
    int s = src[e];
    unsigned v = __ldg(&g_v[s]);
    int pos = atomicAdd(&g_cursor[dst[e]], 1);
    g_csr2[pos] = make_int2(s, (int)v);       // one 8B scattered write = one sector
}

// ---------------- layer-1 gather: smem EW table, zero random loads ----------
__global__ __launch_bounds__(256) void k_gather1(const float* __restrict__ b1) {
    __shared__ float sEW[VOCAB * HID];        // 8KB
    const float* ew = (const float*)g_EW;
    for (int k = threadIdx.x; k < VOCAB * HID; k += 256) sEW[k] = ew[k];
    __syncthreads();

    int n = (blockIdx.x * blockDim.x + threadIdx.x) >> 5;
    if (n >= N_NODES) return;
    int lane = threadIdx.x & 31;
    int eq = lane >> 2, fj = lane & 3;
    int off = __ldg(&g_off[n]);
    int deg = __ldg(&g_deg[n]);

    float4 acc = make_float4(0.f, 0.f, 0.f, 0.f);
    for (int base = 0; base < deg; base += 8) {
        int e = base + eq;
        if (e < deg) {
            int2 c = __ldg(&g_csr2[off + e]);
            unsigned vb = (unsigned)c.y;
            int   xs = vb & 0x7Fu;
            float ds = __uint_as_float(vb & ~0x7Fu);
            float4 w = *(const float4*)&sEW[xs * HID + fj * 4];
            acc.x = fmaf(w.x, ds, acc.x);
            acc.y = fmaf(w.y, ds, acc.y);
            acc.z = fmaf(w.z, ds, acc.z);
            acc.w = fmaf(w.w, ds, acc.w);
        }
    }
#pragma unroll
    for (int o = 16; o >= 4; o >>= 1) {
        acc.x += __shfl_down_sync(0xffffffffu, acc.x, o);
        acc.y += __shfl_down_sync(0xffffffffu, acc.y, o);
        acc.z += __shfl_down_sync(0xffffffffu, acc.z, o);
        acc.w += __shfl_down_sync(0xffffffffu, acc.w, o);
    }
    if (lane < 4) {
        float di = __ldg(&g_dinv[n]);
        unsigned vn = __ldg(&g_v[n]);
        float4 ws = *(const float4*)&sEW[(vn & 0x7Fu) * HID + lane * 4];
        float4 b  = __ldg((const float4*)b1 + lane);
        float4 h;
        h.x = fmaxf((acc.x + ws.x * di) * di + b.x, 0.0f);   // self loop: dinv^2 (exact)
        h.y = fmaxf((acc.y + ws.y * di) * di + b.y, 0.0f);
        h.z = fmaxf((acc.z + ws.z * di) * di + b.z, 0.0f);
        h.w = fmaxf((acc.w + ws.w * di) * di + b.w, 0.0f);
        g_h1[n * 4 + lane] = h;
    }
}

// a2[i] = (h1[i] @ W2) * dinv[i]
__global__ __launch_bounds__(256) void k_l2(const float* __restrict__ W2) {
    __shared__ float sW[HID * HID];
    if (threadIdx.x < HID * HID) sW[threadIdx.x] = W2[threadIdx.x];
    __syncthreads();
    int i = blockIdx.x * blockDim.x + threadIdx.x;
    if (i >= N_NODES) return;
    float h[HID];
#pragma unroll
    for (int q = 0; q < 4; q++) {
        float4 v = g_h1[i * 4 + q];
        h[4 * q + 0] = v.x; h[4 * q + 1] = v.y; h[4 * q + 2] = v.z; h[4 * q + 3] = v.w;
    }
    float o[HID];
#pragma unroll
    for (int j = 0; j < HID; j++) o[j] = 0.0f;
#pragma unroll
    for (int k = 0; k < HID; k++)
#pragma unroll
        for (int j = 0; j < HID; j++) o[j] = fmaf(h[k], sW[k * HID + j], o[j]);
    float di = g_dinv[i];
#pragma unroll
    for (int q = 0; q < 4; q++)
        g_a2[i * 4 + q] = make_float4(o[4*q]*di, o[4*q+1]*di, o[4*q+2]*di, o[4*q+3]*di);
}

// layer-2 gather: warp per node, 4 lanes per edge, random a2 rows (L2-resident)
__global__ __launch_bounds__(256) void k_gather2(const float* __restrict__ b2) {
    int n = (blockIdx.x * blockDim.x + threadIdx.x) >> 5;
    if (n >= N_NODES) return;
    int lane = threadIdx.x & 31;
    int eq = lane >> 2, fj = lane & 3;
    int off = __ldg(&g_off[n]);
    int deg = __ldg(&g_deg[n]);

    float4 acc = make_float4(0.f, 0.f, 0.f, 0.f);
    for (int base = 0; base < deg; base += 8) {
        int e = base + eq;
        if (e < deg) {
            int s = __ldg(&g_csr2[off + e]).x;
            float4 v = __ldg(&g_a2[s * 4 + fj]);
            acc.x += v.x; acc.y += v.y; acc.z += v.z; acc.w += v.w;
        }
    }
#pragma unroll
    for (int o = 16; o >= 4; o >>= 1) {
        acc.x += __shfl_down_sync(0xffffffffu, acc.x, o);
        acc.y += __shfl_down_sync(0xffffffffu, acc.y, o);
        acc.z += __shfl_down_sync(0xffffffffu, acc.z, o);
        acc.w += __shfl_down_sync(0xffffffffu, acc.w, o);
    }
    if (lane < 4) {
        float di = __ldg(&g_dinv[n]);
        float4 self = __ldg(&g_a2[n * 4 + lane]);
        float4 b = __ldg((const float4*)b2 + lane);
        float4 o;
        o.x = fmaxf((acc.x + self.x) * di + b.x, 0.0f);
        o.y = fmaxf((acc.y + self.y) * di + b.y, 0.0f);
        o.z = fmaxf((acc.z + self.z) * di + b.z, 0.0f);
        o.w = fmaxf((acc.w + self.w) * di + b.w, 0.0f);
        g_h2[n * 4 + lane] = o;
    }
}

// pooling: batch sorted -> warp-uniform segments reduce via shuffles
__global__ __launch_bounds__(256) void k_pool(const int* __restrict__ batch) {
    int i = blockIdx.x * blockDim.x + threadIdx.x;
    int lane = threadIdx.x & 31;
    float h[HID];
    int b = -1;
    if (i < N_NODES) {
        b = batch[i];
#pragma unroll
        for (int q = 0; q < 4; q++) {
            float4 v = g_h2[i * 4 + q];
            h[4*q+0] = v.x; h[4*q+1] = v.y; h[4*q+2] = v.z; h[4*q+3] = v.w;
        }
    } else {
#pragma unroll
        for (int k = 0; k < HID; k++) h[k] = 0.0f;
    }
    int b0 = __shfl_sync(0xffffffffu, b, 0);
    bool uniform = __all_sync(0xffffffffu, b == b0);
    if (uniform && b0 >= 0) {
#pragma unroll
        for (int k = 0; k < HID; k++) {
#pragma unroll
            for (int off = 16; off > 0; off >>= 1)
                h[k] += __shfl_down_sync(0xffffffffu, h[k], off);
        }
        if (lane == 0) {
            float4* p = (float4*)&g_sums[b0 * HID];
#pragma unroll
            for (int q = 0; q < 4; q++)
                red4(p + q, h[4*q], h[4*q+1], h[4*q+2], h[4*q+3]);
            atomicAdd(&g_cnt[b0], 32.0f);
        }
    } else if (b >= 0) {
        float4* p = (float4*)&g_sums[b * HID];
#pragma unroll
        for (int q = 0; q < 4; q++)
            red4(p + q, h[4*q], h[4*q+1], h[4*q+2], h[4*q+3]);
        atomicAdd(&g_cnt[b], 1.0f);
    }
}

__global__ __launch_bounds__(256) void k_final(const float* __restrict__ Wc,
                                               const float* __restrict__ bc,
                                               float* __restrict__ out) {
    int g = blockIdx.x * blockDim.x + threadIdx.x;
    if (g >= N_GRAPHS) return;
    float inv = 1.0f / fmaxf(g_cnt[g], 1.0f);
    float p[HID];
#pragma unroll
    for (int k = 0; k < HID; k++) p[k] = g_sums[g * HID + k] * inv;
#pragma unroll
    for (int j = 0; j < LABELS; j++) {
        float s = __ldg(&bc[j]);
#pragma unroll
        for (int k = 0; k < HID; k++) s = fmaf(p[k], __ldg(&Wc[k * LABELS + j]), s);
        out[g * LABELS + j] = s;
    }
}

// ---------------- launch -----------------------------------------------------
extern "C" void kernel_launch(void* const* d_in, const int* in_sizes, int n_in,
                              void* d_out, int out_size) {
    const int*   x    = (const int*)  d_in[0];
    const int*   ei   = (const int*)  d_in[1];
    const int*   batch= (const int*)  d_in[2];
    const float* emb  = (const float*)d_in[3];
    const float* W1   = (const float*)d_in[4];
    const float* b1   = (const float*)d_in[5];
    const float* W2   = (const float*)d_in[6];
    const float* b2   = (const float*)d_in[7];
    const float* Wc   = (const float*)d_in[8];
    const float* bc   = (const float*)d_in[9];
    float* out = (float*)d_out;

    int E = in_sizes[1] / 2;
    const int* src = ei;
    const int* dst = ei + E;

    int gn = (N_NODES + 255) / 256;
    int ge = (E + 255) / 256;
    int gw = (N_NODES * 32 + 255) / 256;     // warp per node

    k_init     <<<gn, 256>>>();
    k_deg      <<<ge, 256>>>(dst, E);
    k_scan1    <<<SCAN_NB, SCAN_BLK>>>();
    k_scan2_ew <<<2, 128>>>(emb, W1);
    k_scan3_v  <<<gn, 256>>>(x);
    k_scatter  <<<ge, 256>>>(src, dst, E);
    k_gather1  <<<gw, 256>>>(b1);
    k_l2       <<<gn, 256>>>(W2);
    k_gather2  <<<gw, 256>>>(b2);
    k_pool     <<<gn, 256>>>(batch);
    k_final    <<<(N_GRAPHS + 255) / 256, 256>>>(Wc, bc, out);
}